// round 5
// baseline (speedup 1.0000x reference)
#include <cuda_runtime.h>

#define IMG_H 512
#define IMG_W 512
#define N_PLANES 256          // B*C = 8*32
#define BAND_ROWS 172
#define N_BANDS 3             // 3*172 = 516 >= 512
#define N_ITERS (BAND_ROWS + 8)   // 180, multiple of 10
#define TPB 128               // 128 threads * 4 cols = 512 cols

__device__ double g_acc;

__global__ void sc_init() {
    if (threadIdx.x == 0) g_acc = 0.0;
}

__global__ void sc_final(float* out) {
    if (threadIdx.x == 0) out[0] = (float)(g_acc * 0.125);  // mean over batch of 8
}

// Load one padded row (only called when the row is in-image).
__device__ __forceinline__ void load_row(
    const float4* __restrict__ rp, bool t0, bool t127,
    float4& vL, float4& vC, float4& vR)
{
    vC = __ldg(rp);
    if (t0)   vL = make_float4(0.f, 0.f, 0.f, 0.f);
    else      vL = __ldg(rp - 1);
    if (t127) vR = make_float4(0.f, 0.f, 0.f, 0.f);
    else      vR = __ldg(rp + 1);
}

__device__ __forceinline__ void load_or_zero(
    const float4* __restrict__ row0, int Ln, int rowStart, bool t0, bool t127,
    float4& vL, float4& vC, float4& vR)
{
    if ((unsigned)Ln < (unsigned)IMG_H) {
        load_row(row0 + (size_t)(Ln - (rowStart - 4)) * (IMG_W / 4), t0, t127, vL, vC, vR);
    } else {
        vL = vC = vR = make_float4(0.f, 0.f, 0.f, 0.f);
    }
}

__global__ void __launch_bounds__(TPB, 6) sc_main(const float* __restrict__ img) {
    const int tid   = threadIdx.x;
    const int plane = blockIdx.x;
    const int band  = blockIdx.y;
    const int rowStart = band * BAND_ROWS;
    const int c0 = tid << 2;
    const float* base = img + (size_t)plane * (IMG_H * IMG_W);

    const bool t0   = (tid == 0);
    const bool t127 = (tid == TPB - 1);
    const bool thB  = t0 || t127;

    // cnt_w per owned column (window-overlap count along W); 9 in interior
    const float cw0 = (float)(min(c0 + 0, 4) + min(IMG_W - 1 - (c0 + 0), 4) + 1);
    const float cw1 = (float)(min(c0 + 1, 4) + min(IMG_W - 1 - (c0 + 1), 4) + 1);
    const float cw2 = (float)(min(c0 + 2, 4) + min(IMG_W - 1 - (c0 + 2), 4) + 1);
    const float cw3 = (float)(min(c0 + 3, 4) + min(IMG_W - 1 - (c0 + 3), 4) + 1);

    // horizontal-9-sum ring in SMEM (private slot per thread, no barriers)
    __shared__ float4 hs[10][TPB];
#pragma unroll
    for (int i = 0; i < 10; i++) hs[i][tid] = make_float4(0.f, 0.f, 0.f, 0.f);

    float4 xring[5];    // raw x, delayed 4 rows (registers)
#pragma unroll
    for (int i = 0; i < 5; i++)  xring[i] = make_float4(0.f, 0.f, 0.f, 0.f);
    float4 S = make_float4(0.f, 0.f, 0.f, 0.f);   // vertical 9-sum of hsum

    float acc_sq = 0.f;   // sum of x^2
    float acc_xs = 0.f;   // sum of x * S
    float acc_c  = 0.f;   // border correction: sum (81 - cnth*cw) * x^2

    const float4* row0 = (const float4*)(base) + (size_t)(rowStart - 4) * (IMG_W / 4) + tid;

    // software pipeline, depth 2: rows i and i+1 in flight
    float4 cvL, cvC, cvR;   // row i   (consume now)
    float4 pvL, pvC, pvR;   // row i+1 (arrives next)
    load_or_zero(row0, rowStart - 4, rowStart, t0, t127, cvL, cvC, cvR);
    load_or_zero(row0, rowStart - 3, rowStart, t0, t127, pvL, pvC, pvR);

    for (int it = 0; it < N_ITERS / 10; ++it) {
#pragma unroll
        for (int k = 0; k < 10; ++k) {
            const int i = it * 10 + k;

            // prefetch row i+2 — two rows ahead of consumption
            float4 nvL, nvC, nvR;
            load_or_zero(row0, rowStart - 2 + i, rowStart, t0, t127, nvL, nvC, nvR);

            // horizontal 9-sums for the 4 owned columns (sliding)
            float s8 = ((cvL.x + cvL.y) + (cvL.z + cvL.w))
                     + ((cvC.x + cvC.y) + (cvC.z + cvC.w)) + cvR.x;
            float4 hn;
            hn.x = s8;
            hn.y = hn.x - cvL.x + cvR.y;
            hn.z = hn.y - cvL.y + cvR.z;
            hn.w = hn.z - cvL.z + cvR.w;

            // slide vertical sum: S covers hsum rows [L-8, L] after update
            const float4 hold = hs[(k + 1) % 10][tid];   // hsum row L-9
            S.x += hn.x - hold.x;
            S.y += hn.y - hold.y;
            S.z += hn.z - hold.z;
            S.w += hn.w - hold.w;
            hs[k][tid] = hn;

            const float4 xe = xring[(k + 1) % 5];        // x at row r = L-4
            xring[k % 5] = cvC;

            // advance pipeline
            cvL = pvL; cvC = pvC; cvR = pvR;
            pvL = nvL; pvC = nvC; pvR = nvR;

            // emit row r = rowStart - 8 + i
            const int r = rowStart - 8 + i;
            if (i >= 8 && r < IMG_H) {
                acc_sq = fmaf(xe.x, xe.x, acc_sq);
                acc_sq = fmaf(xe.y, xe.y, acc_sq);
                acc_sq = fmaf(xe.z, xe.z, acc_sq);
                acc_sq = fmaf(xe.w, xe.w, acc_sq);
                acc_xs = fmaf(xe.x, S.x, acc_xs);
                acc_xs = fmaf(xe.y, S.y, acc_xs);
                acc_xs = fmaf(xe.z, S.z, acc_xs);
                acc_xs = fmaf(xe.w, S.w, acc_xs);

                const bool rowB = (r < 4) | (r > IMG_H - 5);
                if (rowB | thB) {
                    const float cnth = (float)(min(r, 4) + min(IMG_H - 1 - r, 4) + 1);
                    float c;
                    c = 81.0f - cnth * cw0; acc_c = fmaf(c, xe.x * xe.x, acc_c);
                    c = 81.0f - cnth * cw1; acc_c = fmaf(c, xe.y * xe.y, acc_c);
                    c = 81.0f - cnth * cw2; acc_c = fmaf(c, xe.z * xe.z, acc_c);
                    c = 81.0f - cnth * cw3; acc_c = fmaf(c, xe.w * xe.w, acc_c);
                }
            }
        }
    }

    // per-thread combine: (81+cnth*cw)x^2 - 2xS  ==  162x^2 - corr - 2xS
    float acc = fmaf(162.0f, acc_sq, fmaf(-2.0f, acc_xs, -acc_c));

    // block reduction: warp shuffle -> smem -> one double atomic per CTA
    __shared__ float warpsum[TPB / 32];
    float v = acc;
#pragma unroll
    for (int off = 16; off; off >>= 1) v += __shfl_down_sync(0xffffffffu, v, off);
    if ((tid & 31) == 0) warpsum[tid >> 5] = v;
    __syncthreads();
    if (tid == 0) {
        float s = warpsum[0] + warpsum[1] + warpsum[2] + warpsum[3];
        atomicAdd(&g_acc, (double)s);
    }
}

extern "C" void kernel_launch(void* const* d_in, const int* in_sizes, int n_in,
                              void* d_out, int out_size) {
    const float* img = (const float*)d_in[0];
    sc_init<<<1, 32>>>();
    dim3 grid(N_PLANES, N_BANDS);
    sc_main<<<grid, TPB>>>(img);
    sc_final<<<1, 32>>>((float*)d_out);
}

// round 6
// speedup vs baseline: 1.1405x; 1.1405x over previous
#include <cuda_runtime.h>

#define TPB 64            // 2 independent warps per CTA
#define IMG_H 512
#define IMG_W 512
#define N_ITERS 140       // 128 emit rows + 8 halo + 4 pipeline slack

__device__ double g_acc = 0.0;

__global__ void sc_final(float* out) {
    if (threadIdx.x == 0) {
        out[0] = (float)(g_acc * 0.125);   // mean over batch of 8
        g_acc = 0.0;                        // reset for next launch (deterministic)
    }
}

// Each warp scans a 256-col x 128-row region. Lane owns 8 contiguous columns
// (two aligned float4s A,B). Neighbor halos via warp shuffle; warp-edge lanes
// patch with one predicated LDG.
__global__ void __launch_bounds__(TPB, 7) sc_main(const float* __restrict__ img) {
    const int tid  = threadIdx.x;
    const int lane = tid & 31;
    const int wid  = tid >> 5;
    const int plane   = blockIdx.x;
    const int region  = blockIdx.y * 2 + wid;   // 0..7
    const int colhalf = region & 1;
    const int vband   = region >> 1;            // 0..3
    const int rowStart = vband * 128;

    const float4* base4 = (const float4*)img + (size_t)plane * (IMG_H * (IMG_W / 4));
    const int iA = colhalf * 64 + 2 * lane;     // own float4 index within row

    const bool haloAct = (lane == 0 && colhalf == 1) || (lane == 31 && colhalf == 0);
    const int  hOff    = (lane == 0) ? -1 : 2;  // halo float4 offset (lane0 / lane31)

    // column-border weights: w(col) = 9 - cw(col) = max(4-col,0)+max(col-507,0)
    // nonzero only for global cols 0..3 (lane0,colhalf0 -> in A) and 508..511
    // (lane31,colhalf1 -> in B). xs selects the matching float4 at emit time.
    const int cbase = colhalf * 256 + 8 * lane;
    const int cj = (colhalf == 0) ? cbase : cbase + 4;
    float4 w4;
    w4.x = (float)(max(4 - (cj + 0), 0) + max((cj + 0) - 507, 0));
    w4.y = (float)(max(4 - (cj + 1), 0) + max((cj + 1) - 507, 0));
    w4.z = (float)(max(4 - (cj + 2), 0) + max((cj + 2) - 507, 0));
    w4.w = (float)(max(4 - (cj + 3), 0) + max((cj + 3) - 507, 0));

    // horizontal-sum ring (delay 9), fp32, thread-private slots, no barriers
    __shared__ float4 ringA[10][TPB];
    __shared__ float4 ringB[10][TPB];
#pragma unroll
    for (int i = 0; i < 10; i++) {
        ringA[i][tid] = make_float4(0.f, 0.f, 0.f, 0.f);
        ringB[i][tid] = make_float4(0.f, 0.f, 0.f, 0.f);
    }

    float4 xrA[5], xrB[5];     // raw x, delay 4, registers
#pragma unroll
    for (int i = 0; i < 5; i++) {
        xrA[i] = make_float4(0.f, 0.f, 0.f, 0.f);
        xrB[i] = make_float4(0.f, 0.f, 0.f, 0.f);
    }
    float4 Sa = make_float4(0.f, 0.f, 0.f, 0.f);   // vertical 9-sum of h, cols 0-3
    float4 Sb = make_float4(0.f, 0.f, 0.f, 0.f);   // cols 4-7

    float acc_sq = 0.f, acc_xs = 0.f, acc_w = 0.f, acc_c = 0.f;

    // pipeline depth 1: load row 0
    float4 cA, cB, cH, nA, nB, nH;
    {
        const int L = rowStart - 4;
        if ((unsigned)L < (unsigned)IMG_H) {
            const float4* p = base4 + (size_t)L * (IMG_W / 4) + iA;
            cA = __ldg(p); cB = __ldg(p + 1);
            cH = haloAct ? __ldg(p + hOff) : make_float4(0.f, 0.f, 0.f, 0.f);
        } else {
            cA = cB = cH = make_float4(0.f, 0.f, 0.f, 0.f);
        }
    }

    for (int it = 0; it < N_ITERS / 10; ++it) {
#pragma unroll
        for (int k = 0; k < 10; ++k) {
            const int i = it * 10 + k;

            // prefetch row i+1
            {
                const int L = rowStart - 3 + i;
                if ((unsigned)L < (unsigned)IMG_H) {
                    const float4* p = base4 + (size_t)L * (IMG_W / 4) + iA;
                    nA = __ldg(p); nB = __ldg(p + 1);
                    nH = haloAct ? __ldg(p + hOff) : make_float4(0.f, 0.f, 0.f, 0.f);
                } else {
                    nA = nB = nH = make_float4(0.f, 0.f, 0.f, 0.f);
                }
            }

            // halos for current row: vL = lane-1's B, vR = lane+1's A
            float4 vL, vR;
            vL.x = __shfl_up_sync(0xffffffffu, cB.x, 1);
            vL.y = __shfl_up_sync(0xffffffffu, cB.y, 1);
            vL.z = __shfl_up_sync(0xffffffffu, cB.z, 1);
            vL.w = __shfl_up_sync(0xffffffffu, cB.w, 1);
            vR.x = __shfl_down_sync(0xffffffffu, cA.x, 1);
            vR.y = __shfl_down_sync(0xffffffffu, cA.y, 1);
            vR.z = __shfl_down_sync(0xffffffffu, cA.z, 1);
            vR.w = __shfl_down_sync(0xffffffffu, cA.w, 1);
            if (lane == 0)  vL = cH;   // cH==0 when out-of-image
            if (lane == 31) vR = cH;

            // horizontal 9-sums, 8 owned columns, sliding
            float h0 = ((vL.x + vL.y) + (vL.z + vL.w))
                     + ((cA.x + cA.y) + (cA.z + cA.w)) + cB.x;
            float h1 = h0 - vL.x + cB.y;
            float h2 = h1 - vL.y + cB.z;
            float h3 = h2 - vL.z + cB.w;
            float h4 = h3 - vL.w + vR.x;
            float h5 = h4 - cA.x + vR.y;
            float h6 = h5 - cA.y + vR.z;
            float h7 = h6 - cA.z + vR.w;

            // vertical slide: S += h(L) - h(L-9)
            const float4 oA = ringA[(k + 1) % 10][tid];
            const float4 oB = ringB[(k + 1) % 10][tid];
            Sa.x += h0 - oA.x;  Sa.y += h1 - oA.y;
            Sa.z += h2 - oA.z;  Sa.w += h3 - oA.w;
            Sb.x += h4 - oB.x;  Sb.y += h5 - oB.y;
            Sb.z += h6 - oB.z;  Sb.w += h7 - oB.w;
            ringA[k][tid] = make_float4(h0, h1, h2, h3);
            ringB[k][tid] = make_float4(h4, h5, h6, h7);

            const float4 xa = xrA[(k + 1) % 5];   // x at emit row (delay 4)
            const float4 xb = xrB[(k + 1) % 5];
            xrA[k % 5] = cA;
            xrB[k % 5] = cB;

            cA = nA; cB = nB; cH = nH;

            // emit row r = rowStart - 8 + i, exactly rows [rowStart, rowStart+128)
            if (i >= 8 && i < 136) {
                acc_sq = fmaf(xa.x, xa.x, acc_sq);
                acc_sq = fmaf(xa.y, xa.y, acc_sq);
                acc_sq = fmaf(xa.z, xa.z, acc_sq);
                acc_sq = fmaf(xa.w, xa.w, acc_sq);
                acc_sq = fmaf(xb.x, xb.x, acc_sq);
                acc_sq = fmaf(xb.y, xb.y, acc_sq);
                acc_sq = fmaf(xb.z, xb.z, acc_sq);
                acc_sq = fmaf(xb.w, xb.w, acc_sq);
                acc_xs = fmaf(xa.x, Sa.x, acc_xs);
                acc_xs = fmaf(xa.y, Sa.y, acc_xs);
                acc_xs = fmaf(xa.z, Sa.z, acc_xs);
                acc_xs = fmaf(xa.w, Sa.w, acc_xs);
                acc_xs = fmaf(xb.x, Sb.x, acc_xs);
                acc_xs = fmaf(xb.y, Sb.y, acc_xs);
                acc_xs = fmaf(xb.z, Sb.z, acc_xs);
                acc_xs = fmaf(xb.w, Sb.w, acc_xs);

                // column-border weighted x^2 (zero for all but one lane/warp)
                const float4 xs = (colhalf == 0) ? xa : xb;
                acc_w = fmaf(w4.x * xs.x, xs.x, acc_w);
                acc_w = fmaf(w4.y * xs.y, xs.y, acc_w);
                acc_w = fmaf(w4.z * xs.z, xs.z, acc_w);
                acc_w = fmaf(w4.w * xs.w, xs.w, acc_w);

                const int r = rowStart - 8 + i;
                const bool rowB = (r < 4) | (r > IMG_H - 5);
                if (rowB) {   // uniform branch, 8 rows per band max
                    float rowsq = 0.f, roww = 0.f;
                    rowsq += xa.x * xa.x + xa.y * xa.y + xa.z * xa.z + xa.w * xa.w;
                    rowsq += xb.x * xb.x + xb.y * xb.y + xb.z * xb.z + xb.w * xb.w;
                    roww  = fmaf(w4.x * xs.x, xs.x, roww);
                    roww  = fmaf(w4.y * xs.y, xs.y, roww);
                    roww  = fmaf(w4.z * xs.z, xs.z, roww);
                    roww  = fmaf(w4.w * xs.w, xs.w, roww);
                    const float cnth = (float)(min(r, 4) + min(IMG_H - 1 - r, 4) + 1);
                    acc_c = fmaf(9.0f - cnth, fmaf(9.0f, rowsq, -roww), acc_c);
                }
            }
        }
    }

    // total = 162*x^2 - 2*x*S - [9*acc_w + acc_c]   (border corrections)
    float acc = fmaf(162.0f, acc_sq, fmaf(-2.0f, acc_xs, -fmaf(9.0f, acc_w, acc_c)));

    // warp reduce + one double atomic per warp (warps are independent)
#pragma unroll
    for (int off = 16; off; off >>= 1) acc += __shfl_down_sync(0xffffffffu, acc, off);
    if (lane == 0) atomicAdd(&g_acc, (double)acc);
}

extern "C" void kernel_launch(void* const* d_in, const int* in_sizes, int n_in,
                              void* d_out, int out_size) {
    const float* img = (const float*)d_in[0];
    dim3 grid(256, 4);          // 256 planes x (4 blockIdx.y * 2 warps = 8 regions)
    sc_main<<<grid, TPB>>>(img);
    sc_final<<<1, 32>>>((float*)d_out);
}